// round 10
// baseline (speedup 1.0000x reference)
#include <cuda_runtime.h>
#include <cuda_fp16.h>
#include <cstdint>

#define MDIM 8192
#define NDIM 4096
#define KDIM 4096
#define BM 128
#define BN 256
#define BK 64
#define STAGES 4
#define KITERS (KDIM / BK)              /* 64 */
#define A_BYTES (BM * BK * 2)           /* 16384 */
#define B_BYTES (BN * BK * 2)           /* 32768 */
#define STAGE_BYTES (A_BYTES + B_BYTES) /* 49152 */
#define SMEM_TOTAL (STAGES * STAGE_BYTES) /* 196608 */

// Scratch: fp16(rn)-rounded, k-permuted operands (same permutation on A and B).
__device__ __half g_wt[(size_t)NDIM * KDIM];  // W^T: [n][k]
__device__ __half g_xp[(size_t)MDIM * KDIM];  // x:   [m][k]

// ---------------- helpers ----------------
__device__ __forceinline__ uint32_t smem_u32(const void* p) {
    uint32_t a;
    asm("{ .reg .u64 t; cvta.to.shared.u64 t, %1; cvt.u32.u64 %0, t; }" : "=r"(a) : "l"(p));
    return a;
}
__device__ __forceinline__ uint4 lds128(uint32_t a) {
    uint4 v;
    asm volatile("ld.shared.v4.b32 {%0,%1,%2,%3}, [%4];"
                 : "=r"(v.x), "=r"(v.y), "=r"(v.z), "=r"(v.w) : "r"(a));
    return v;
}
__device__ __forceinline__ void cp16(uint32_t dst, const void* src) {
    asm volatile("cp.async.cg.shared.global [%0], [%1], 16;" :: "r"(dst), "l"(src) : "memory");
}
// fp16-accumulator MMA: D,C are 2 b32 regs (half2 x2: rows 0-7 / 8-15)
__device__ __forceinline__ void mma16816_h(uint32_t& c0, uint32_t& c1,
                                           uint32_t a0, uint32_t a1, uint32_t a2,
                                           uint32_t a3, uint32_t b0, uint32_t b1) {
    asm volatile(
        "mma.sync.aligned.m16n8k16.row.col.f16.f16.f16.f16 "
        "{%0,%1}, {%2,%3,%4,%5}, {%6,%7}, {%0,%1};"
        : "+r"(c0), "+r"(c1)
        : "r"(a0), "r"(a1), "r"(a2), "r"(a3), "r"(b0), "r"(b1));
}

// ---------------- kernel 1: GPTQ dequant -> fp16, k-permuted W^T ----------------
__global__ void __launch_bounds__(256) dequant_kernel(const int* __restrict__ qw,
                                                      const int* __restrict__ qz,
                                                      const float* __restrict__ sc) {
    int tid = blockIdx.x * 256 + threadIdx.x;   // 2M threads
    int n = tid & (NDIM - 1);
    int rest = tid >> 12;
    int c0 = rest & 3;
    int blk = rest >> 2;                        // 32-k chunk, 0..127
    int grp = blk >> 2;
    int zp = qz[grp * (NDIM / 8) + (n >> 3)];
    int z = ((zp >> ((n & 7) * 4)) & 15) + 1;
    float s = sc[grp * NDIM + n];
    __half2 o[4];
#pragma unroll
    for (int g = 0; g < 4; ++g) {
        int q = qw[(size_t)(blk * 4 + g) * NDIM + n];
        int w0 = (q >> (8 * c0)) & 15;
        int w1 = (q >> (8 * c0 + 4)) & 15;
        o[2 * (g >> 1) + (g & 1)] =
            __floats2half2_rn(s * (float)(w0 - z), s * (float)(w1 - z));
    }
    uint4* dst = (uint4*)((char*)g_wt + (size_t)n * (KDIM * 2) + blk * 64 + c0 * 16);
    *dst = *(uint4*)&o[0];
}

// ---------------- kernel 2: x -> fp16, k-permuted copy ----------------
__global__ void __launch_bounds__(256) xprep_kernel(const float* __restrict__ x) {
    int tid = blockIdx.x * 256 + threadIdx.x;   // 4M threads
    int c0 = tid & 3;
    int blk = (tid >> 2) & 127;
    int m = tid >> 9;
    const float2* src = (const float2*)(x + (size_t)m * KDIM + blk * 32 + 2 * c0);
    __half2 o[4];
#pragma unroll
    for (int u = 0; u < 4; ++u) {
        float2 f = src[4 * u];
        o[u] = __floats2half2_rn(f.x, f.y);
    }
    uint4* dst = (uint4*)((char*)g_xp + (size_t)m * (KDIM * 2) + blk * 64 + c0 * 16);
    *dst = *(uint4*)&o[0];
}

// ---- kernel 3: fp16 mma.sync GEMM, fp16-accum chain(2) + fp32 promotion ----
__global__ void __launch_bounds__(256, 1)
gemm_kernel(const float* __restrict__ bias, float* __restrict__ out) {
    extern __shared__ char smem_raw[];
    uint32_t sbase = smem_u32(smem_raw);
    int tid = threadIdx.x;
    int l = tid & 31;
    int wid = tid >> 5;
    int wm = wid & 1;       // 2 m-warps (64 rows each)
    int wn = wid >> 1;      // 4 n-warps (64 cols each)

    // supertile: 8 m-tiles x 16 n-tiles (full N) -> W (32MB fp16) L2-resident
    int bid = blockIdx.x;
    int sup = bid >> 7;
    int loc = bid & 127;
    int m0 = (sup * 8 + (loc & 7)) * BM;
    int n0 = (loc >> 3) * BN;

    // --- async-copy geometry: 128B rows, 8 x 16B chunks, XOR swizzle ---
    int cr = tid >> 3;      // 0..31
    int cq = tid & 7;
    const char* a_src = (const char*)g_xp + (size_t)(m0 + cr) * (KDIM * 2) + cq * 16;
    const char* b_src = (const char*)g_wt + (size_t)(n0 + cr) * (KDIM * 2) + cq * 16;
    uint32_t a_dst[4], b_dst[8];
#pragma unroll
    for (int i = 0; i < 4; ++i) {
        int r = cr + 32 * i;
        a_dst[i] = (uint32_t)r * 128u + (uint32_t)(cq ^ (r & 7)) * 16u;
    }
#pragma unroll
    for (int i = 0; i < 8; ++i) {
        int r = cr + 32 * i;
        b_dst[i] = (uint32_t)r * 128u + (uint32_t)(cq ^ (r & 7)) * 16u;
    }

    auto fetch = [&](int it) {
        int s = it & (STAGES - 1);
        uint32_t sa = sbase + s * STAGE_BYTES;
        uint32_t sb = sa + A_BYTES;
        const char* ga = a_src + (size_t)it * (BK * 2);
        const char* gb = b_src + (size_t)it * (BK * 2);
#pragma unroll
        for (int i = 0; i < 4; ++i) cp16(sa + a_dst[i], ga + (size_t)i * 32 * (KDIM * 2));
#pragma unroll
        for (int i = 0; i < 8; ++i) cp16(sb + b_dst[i], gb + (size_t)i * 32 * (KDIM * 2));
    };

#pragma unroll
    for (int i = 0; i < STAGES - 1; ++i) {
        fetch(i);
        asm volatile("cp.async.commit_group;" ::: "memory");
    }

    // --- fragment lds addresses (32k-chunk 0; chunk 1 = ^64; row+8 = +1024) ---
    uint32_t a_off[4];
#pragma unroll
    for (int ms = 0; ms < 4; ++ms) {
        int r = wm * 64 + ms * 16 + (l >> 2);
        a_off[ms] = (uint32_t)r * 128u + (uint32_t)((l & 3) ^ (r & 7)) * 16u;
    }
    uint32_t b_off[8];
#pragma unroll
    for (int ns = 0; ns < 8; ++ns) {
        int r = wn * 64 + ns * 8 + (l >> 2);
        b_off[ns] = (uint32_t)r * 128u + (uint32_t)((l & 3) ^ (r & 7)) * 16u;
    }

    float acc[4][8][4];
#pragma unroll
    for (int ms = 0; ms < 4; ++ms)
#pragma unroll
        for (int ns = 0; ns < 8; ++ns)
#pragma unroll
            for (int i = 0; i < 4; ++i) acc[ms][ns][i] = 0.f;

    for (int it = 0; it < KITERS; ++it) {
        asm volatile("cp.async.wait_group %0;" :: "n"(STAGES - 2) : "memory");
        __syncthreads();
        if (it + STAGES - 1 < KITERS) fetch(it + STAGES - 1);
        asm volatile("cp.async.commit_group;" ::: "memory");

        uint32_t sa = sbase + (it & (STAGES - 1)) * STAGE_BYTES;
        uint32_t sb = sa + A_BYTES;
#pragma unroll
        for (int kc = 0; kc < 2; ++kc) {        // two 32-k chunks per BK=64
            uint4 ar[4], a8[4], bf[8];
#pragma unroll
            for (int ms = 0; ms < 4; ++ms) {
                uint32_t a = sa + (a_off[ms] ^ (kc * 64));
                ar[ms] = lds128(a);             // row r   (k-steps 0|1 in .xy|.zw)
                a8[ms] = lds128(a + 1024);      // row r+8
            }
#pragma unroll
            for (int ns = 0; ns < 8; ++ns) bf[ns] = lds128(sb + (b_off[ns] ^ (kc * 64)));
            // per fragment: 2-step fp16 chain (k=32), then promote into fp32 acc
#pragma unroll
            for (int ms = 0; ms < 4; ++ms) {
#pragma unroll
                for (int ns = 0; ns < 8; ++ns) {
                    uint32_t t0 = 0u, t1 = 0u;
                    mma16816_h(t0, t1, ar[ms].x, a8[ms].x, ar[ms].y, a8[ms].y,
                               bf[ns].x, bf[ns].y);
                    mma16816_h(t0, t1, ar[ms].z, a8[ms].z, ar[ms].w, a8[ms].w,
                               bf[ns].z, bf[ns].w);
                    float2 f0 = __half22float2(*(__half2*)&t0);
                    float2 f1 = __half22float2(*(__half2*)&t1);
                    acc[ms][ns][0] += f0.x;
                    acc[ms][ns][1] += f0.y;
                    acc[ms][ns][2] += f1.x;
                    acc[ms][ns][3] += f1.y;
                }
            }
        }
    }

    // --- epilogue: acc + bias -> out ---
#pragma unroll
    for (int ms = 0; ms < 4; ++ms) {
        int row = m0 + wm * 64 + ms * 16 + (l >> 2);
#pragma unroll
        for (int ns = 0; ns < 8; ++ns) {
            int col = n0 + wn * 64 + ns * 8 + 2 * (l & 3);
            float2 b2 = *(const float2*)(bias + col);
            float2 v0 = make_float2(acc[ms][ns][0] + b2.x, acc[ms][ns][1] + b2.y);
            float2 v1 = make_float2(acc[ms][ns][2] + b2.x, acc[ms][ns][3] + b2.y);
            *(float2*)(out + (size_t)row * NDIM + col) = v0;
            *(float2*)(out + (size_t)(row + 8) * NDIM + col) = v1;
        }
    }
}

// ---------------- launch ----------------
extern "C" void kernel_launch(void* const* d_in, const int* in_sizes, int n_in,
                              void* d_out, int out_size) {
    const float* x    = (const float*)d_in[0];
    const int*   qw   = (const int*)d_in[1];
    const int*   qz   = (const int*)d_in[2];
    const float* sc   = (const float*)d_in[3];
    const float* bias = (const float*)d_in[4];
    float* out = (float*)d_out;

    dequant_kernel<<<(NDIM * 128 * 4) / 256, 256>>>(qw, qz, sc);
    xprep_kernel<<<(MDIM * 128 * 4) / 256, 256>>>(x);

    cudaFuncSetAttribute(gemm_kernel, cudaFuncAttributeMaxDynamicSharedMemorySize, SMEM_TOTAL);
    gemm_kernel<<<(MDIM / BM) * (NDIM / BN), 256, SMEM_TOTAL>>>(bias, out);
}

// round 11
// speedup vs baseline: 1.3563x; 1.3563x over previous
#include <cuda_runtime.h>
#include <cuda_fp16.h>
#include <cstdint>

#define MDIM 8192
#define NDIM 4096
#define KDIM 4096
#define BM 128
#define BN 256
#define BK 64
#define STAGES 4
#define KITERS (KDIM / BK)              /* 64 */
#define A_BYTES (BM * BK * 2)           /* 16384 */
#define B_BYTES (BN * BK * 2)           /* 32768 */
#define STAGE_BYTES (A_BYTES + B_BYTES) /* 49152 */
#define SMEM_TOTAL (STAGES * STAGE_BYTES) /* 196608 */

#define DQ_BLOCKS (NDIM * 128 * 4 / 256)   /* 8192  */
#define XP_BLOCKS (MDIM * 128 * 4 / 256)   /* 16384 */

// Scratch: fp16(rn)-rounded, k-permuted operands (same permutation on A and B).
__device__ __half g_wt[(size_t)NDIM * KDIM];  // W^T: [n][k]
__device__ __half g_xp[(size_t)MDIM * KDIM];  // x:   [m][k]

// ---------------- helpers ----------------
__device__ __forceinline__ uint32_t smem_u32(const void* p) {
    uint32_t a;
    asm("{ .reg .u64 t; cvta.to.shared.u64 t, %1; cvt.u32.u64 %0, t; }" : "=r"(a) : "l"(p));
    return a;
}
__device__ __forceinline__ uint4 lds128(uint32_t a) {
    uint4 v;
    asm volatile("ld.shared.v4.b32 {%0,%1,%2,%3}, [%4];"
                 : "=r"(v.x), "=r"(v.y), "=r"(v.z), "=r"(v.w) : "r"(a));
    return v;
}
__device__ __forceinline__ void cp16(uint32_t dst, const void* src) {
    asm volatile("cp.async.cg.shared.global [%0], [%1], 16;" :: "r"(dst), "l"(src) : "memory");
}
__device__ __forceinline__ void mma16816(float* d, uint32_t a0, uint32_t a1, uint32_t a2,
                                         uint32_t a3, uint32_t b0, uint32_t b1) {
    asm volatile(
        "mma.sync.aligned.m16n8k16.row.col.f32.f16.f16.f32 "
        "{%0,%1,%2,%3}, {%4,%5,%6,%7}, {%8,%9}, {%0,%1,%2,%3};"
        : "+f"(d[0]), "+f"(d[1]), "+f"(d[2]), "+f"(d[3])
        : "r"(a0), "r"(a1), "r"(a2), "r"(a3), "r"(b0), "r"(b1));
}

// ------- kernel 1: merged prep (dequant W + convert x), concurrent blocks -------
__global__ void __launch_bounds__(256) prep_kernel(const int* __restrict__ qw,
                                                   const int* __restrict__ qz,
                                                   const float* __restrict__ sc,
                                                   const float* __restrict__ x) {
    if (blockIdx.x < DQ_BLOCKS) {
        // --- GPTQ dequant -> fp16, k-permuted W^T ---
        int tid = blockIdx.x * 256 + threadIdx.x;   // 2M threads
        int n = tid & (NDIM - 1);
        int rest = tid >> 12;
        int c0 = rest & 3;
        int blk = rest >> 2;                        // 32-k chunk, 0..127
        int grp = blk >> 2;
        int zp = qz[grp * (NDIM / 8) + (n >> 3)];
        int z = ((zp >> ((n & 7) * 4)) & 15) + 1;
        float s = sc[grp * NDIM + n];
        __half2 o[4];
#pragma unroll
        for (int g = 0; g < 4; ++g) {
            int q = qw[(size_t)(blk * 4 + g) * NDIM + n];
            int w0 = (q >> (8 * c0)) & 15;
            int w1 = (q >> (8 * c0 + 4)) & 15;
            o[2 * (g >> 1) + (g & 1)] =
                __floats2half2_rn(s * (float)(w0 - z), s * (float)(w1 - z));
        }
        uint4* dst = (uint4*)((char*)g_wt + (size_t)n * (KDIM * 2) + blk * 64 + c0 * 16);
        *dst = *(uint4*)&o[0];
    } else {
        // --- x -> fp16, k-permuted copy ---
        int tid = (blockIdx.x - DQ_BLOCKS) * 256 + threadIdx.x;  // 4M threads
        int c0 = tid & 3;
        int blk = (tid >> 2) & 127;
        int m = tid >> 9;
        const float2* src = (const float2*)(x + (size_t)m * KDIM + blk * 32 + 2 * c0);
        __half2 o[4];
#pragma unroll
        for (int u = 0; u < 4; ++u) {
            float2 f = src[4 * u];
            o[u] = __floats2half2_rn(f.x, f.y);
        }
        uint4* dst = (uint4*)((char*)g_xp + (size_t)m * (KDIM * 2) + blk * 64 + c0 * 16);
        *dst = *(uint4*)&o[0];
    }
}

// ---------------- kernel 2: fp16 mma.sync GEMM (proven 838us config) ----------------
__global__ void __launch_bounds__(256, 1)
gemm_kernel(const float* __restrict__ bias, float* __restrict__ out) {
    extern __shared__ char smem_raw[];
    uint32_t sbase = smem_u32(smem_raw);
    int tid = threadIdx.x;
    int l = tid & 31;
    int wid = tid >> 5;
    int wm = wid & 1;       // 2 m-warps (64 rows each)
    int wn = wid >> 1;      // 4 n-warps (64 cols each)

    // supertile: 8 m-tiles x 16 n-tiles (full N) -> W (32MB fp16) L2-resident
    int bid = blockIdx.x;
    int sup = bid >> 7;
    int loc = bid & 127;
    int m0 = (sup * 8 + (loc & 7)) * BM;
    int n0 = (loc >> 3) * BN;

    // --- async-copy geometry: rows of 128B (64 fp16), 8 chunks of 16B, XOR swizzle ---
    int cr = tid >> 3;      // 0..31
    int cq = tid & 7;
    const char* a_src = (const char*)g_xp + (size_t)(m0 + cr) * (KDIM * 2) + cq * 16;
    const char* b_src = (const char*)g_wt + (size_t)(n0 + cr) * (KDIM * 2) + cq * 16;
    uint32_t a_dst[4], b_dst[8];
#pragma unroll
    for (int i = 0; i < 4; ++i) {
        int r = cr + 32 * i;
        a_dst[i] = (uint32_t)r * 128u + (uint32_t)(cq ^ (r & 7)) * 16u;
    }
#pragma unroll
    for (int i = 0; i < 8; ++i) {
        int r = cr + 32 * i;
        b_dst[i] = (uint32_t)r * 128u + (uint32_t)(cq ^ (r & 7)) * 16u;
    }

    auto fetch = [&](int it) {
        int s = it & (STAGES - 1);
        uint32_t sa = sbase + s * STAGE_BYTES;
        uint32_t sb = sa + A_BYTES;
        const char* ga = a_src + (size_t)it * (BK * 2);
        const char* gb = b_src + (size_t)it * (BK * 2);
#pragma unroll
        for (int i = 0; i < 4; ++i) cp16(sa + a_dst[i], ga + (size_t)i * 32 * (KDIM * 2));
#pragma unroll
        for (int i = 0; i < 8; ++i) cp16(sb + b_dst[i], gb + (size_t)i * 32 * (KDIM * 2));
    };

#pragma unroll
    for (int i = 0; i < STAGES - 1; ++i) {
        fetch(i);
        asm volatile("cp.async.commit_group;" ::: "memory");
    }

    // --- fragment lds addresses (32k-chunk 0; chunk 1 = ^64; row+8 = +1024) ---
    uint32_t a_off[4];
#pragma unroll
    for (int ms = 0; ms < 4; ++ms) {
        int r = wm * 64 + ms * 16 + (l >> 2);
        a_off[ms] = (uint32_t)r * 128u + (uint32_t)((l & 3) ^ (r & 7)) * 16u;
    }
    uint32_t b_off[8];
#pragma unroll
    for (int ns = 0; ns < 8; ++ns) {
        int r = wn * 64 + ns * 8 + (l >> 2);
        b_off[ns] = (uint32_t)r * 128u + (uint32_t)((l & 3) ^ (r & 7)) * 16u;
    }

    float acc[4][8][4];
#pragma unroll
    for (int ms = 0; ms < 4; ++ms)
#pragma unroll
        for (int ns = 0; ns < 8; ++ns)
#pragma unroll
            for (int i = 0; i < 4; ++i) acc[ms][ns][i] = 0.f;

    for (int it = 0; it < KITERS; ++it) {
        asm volatile("cp.async.wait_group %0;" :: "n"(STAGES - 2) : "memory");
        __syncthreads();
        if (it + STAGES - 1 < KITERS) fetch(it + STAGES - 1);
        asm volatile("cp.async.commit_group;" ::: "memory");

        uint32_t sa = sbase + (it & (STAGES - 1)) * STAGE_BYTES;
        uint32_t sb = sa + A_BYTES;
#pragma unroll
        for (int kc = 0; kc < 2; ++kc) {        // two 32-k chunks per BK=64
            uint4 ar[4], a8[4], bf[8];
#pragma unroll
            for (int ms = 0; ms < 4; ++ms) {
                uint32_t a = sa + (a_off[ms] ^ (kc * 64));
                ar[ms] = lds128(a);             // row r   (k-steps 0|1 in .xy|.zw)
                a8[ms] = lds128(a + 1024);      // row r+8
            }
#pragma unroll
            for (int ns = 0; ns < 8; ++ns) bf[ns] = lds128(sb + (b_off[ns] ^ (kc * 64)));
            // k-step 0 on all 32 accumulators, then k-step 1
#pragma unroll
            for (int ms = 0; ms < 4; ++ms)
#pragma unroll
                for (int ns = 0; ns < 8; ++ns)
                    mma16816(acc[ms][ns], ar[ms].x, a8[ms].x, ar[ms].y, a8[ms].y,
                             bf[ns].x, bf[ns].y);
#pragma unroll
            for (int ms = 0; ms < 4; ++ms)
#pragma unroll
                for (int ns = 0; ns < 8; ++ns)
                    mma16816(acc[ms][ns], ar[ms].z, a8[ms].z, ar[ms].w, a8[ms].w,
                             bf[ns].z, bf[ns].w);
        }
    }

    // --- epilogue: acc + bias -> out ---
#pragma unroll
    for (int ms = 0; ms < 4; ++ms) {
        int row = m0 + wm * 64 + ms * 16 + (l >> 2);
#pragma unroll
        for (int ns = 0; ns < 8; ++ns) {
            int col = n0 + wn * 64 + ns * 8 + 2 * (l & 3);
            float2 b2 = *(const float2*)(bias + col);
            float2 v0 = make_float2(acc[ms][ns][0] + b2.x, acc[ms][ns][1] + b2.y);
            float2 v1 = make_float2(acc[ms][ns][2] + b2.x, acc[ms][ns][3] + b2.y);
            *(float2*)(out + (size_t)row * NDIM + col) = v0;
            *(float2*)(out + (size_t)(row + 8) * NDIM + col) = v1;
        }
    }
}

// ---------------- launch ----------------
extern "C" void kernel_launch(void* const* d_in, const int* in_sizes, int n_in,
                              void* d_out, int out_size) {
    const float* x    = (const float*)d_in[0];
    const int*   qw   = (const int*)d_in[1];
    const int*   qz   = (const int*)d_in[2];
    const float* sc   = (const float*)d_in[3];
    const float* bias = (const float*)d_in[4];
    float* out = (float*)d_out;

    prep_kernel<<<DQ_BLOCKS + XP_BLOCKS, 256>>>(qw, qz, sc, x);

    cudaFuncSetAttribute(gemm_kernel, cudaFuncAttributeMaxDynamicSharedMemorySize, SMEM_TOTAL);
    gemm_kernel<<<(MDIM / BM) * (NDIM / BN), 256, SMEM_TOTAL>>>(bias, out);
}